// round 9
// baseline (speedup 1.0000x reference)
#include <cuda_runtime.h>
#include <cuda_bf16.h>
#include <math.h>

// RankingLoss: B=65536 rows, C=1024 classes, float32 scores, int32 labels.
// loss = mean_b [ log1p(exp(2*(2.5 - s_pos))) + log1p(exp(2*(0.5 + s_neg))) ]
// Persistent + software-pipelined across rows: a warp always has >=2
// load-batches (2KB) in flight, including through the warp reduction and
// row transition, so DRAM never sees per-warp drain bubbles.

#define NUM_B 65536
#define NUM_C 1024
#define WARPS_PER_BLOCK 8
#define GRID_CTAS (148 * 8)
#define NWARPS (GRID_CTAS * WARPS_PER_BLOCK)   // 9472

__device__ double g_acc = 0.0;
__device__ unsigned int g_done = 0;

__device__ __forceinline__ float softplus_g(float t) {
    return (t > 20.0f) ? t : log1pf(__expf(t));
}

__device__ __forceinline__ void consume_f4(float4 v, int f4, int lbl,
                                           float& vmax, float& spos) {
    const int col = f4 * 4;
    float a0 = v.x, a1 = v.y, a2 = v.z, a3 = v.w;
    if (col + 0 == lbl) { spos = a0; a0 = -INFINITY; }
    if (col + 1 == lbl) { spos = a1; a1 = -INFINITY; }
    if (col + 2 == lbl) { spos = a2; a2 = -INFINITY; }
    if (col + 3 == lbl) { spos = a3; a3 = -INFINITY; }
    vmax = fmaxf(vmax, fmaxf(fmaxf(a0, a1), fmaxf(a2, a3)));
}

struct F8 { float4 a, b; };   // one batch: 2 float4 per lane (8 regs)

__device__ __forceinline__ F8 load_b(const float4* __restrict__ rp,
                                     int b, int lane) {
    F8 r;
    r.a = rp[(2 * b + 0) * 32 + lane];
    r.b = rp[(2 * b + 1) * 32 + lane];
    return r;
}

__device__ __forceinline__ void cons_b(F8 v, int b, int lane, int lbl,
                                       float& vmax, float& spos) {
    consume_f4(v.a, (2 * b + 0) * 32 + lane, lbl, vmax, spos);
    consume_f4(v.b, (2 * b + 1) * 32 + lane, lbl, vmax, spos);
}

__global__ void __launch_bounds__(WARPS_PER_BLOCK * 32)
ranking_loss_kernel(const float* __restrict__ scores,
                    const int* __restrict__ labels,
                    float* __restrict__ out)
{
    const int lane  = threadIdx.x & 31;
    const int warp  = threadIdx.x >> 5;
    int row = blockIdx.x * WARPS_PER_BLOCK + warp;   // < NWARPS < NUM_B

    const float4* rp = (const float4*)(scores + (size_t)row * NUM_C);
    int lbl = labels[row];

    // Prime the pipeline: batches 0,1 of the first row in flight.
    F8 b0 = load_b(rp, 0, lane);
    F8 b1 = load_b(rp, 1, lane);

    float warp_loss = 0.0f;

    for (;;) {
        float vmax = -INFINITY;
        float spos = -INFINITY;

        // Interleave issue/consume so in-flight stays at 2-3 batches and
        // the register peak stays ~24 data regs.
        F8 b2 = load_b(rp, 2, lane);
        cons_b(b0, 0, lane, lbl, vmax, spos);
        F8 b3 = load_b(rp, 3, lane);
        cons_b(b1, 1, lane, lbl, vmax, spos);

        const int  nrow = row + NWARPS;
        const bool more = (nrow < NUM_B);
        const float4* nrp = (const float4*)(scores + (size_t)nrow * NUM_C);
        int nlbl = 0;

        // Prefetch next row's first half + label BEFORE this row's reduce:
        // loads stay outstanding through the shfl chain.
        if (more) { nlbl = labels[nrow]; b0 = load_b(nrp, 0, lane); }
        cons_b(b2, 2, lane, lbl, vmax, spos);
        if (more) { b1 = load_b(nrp, 1, lane); }
        cons_b(b3, 3, lane, lbl, vmax, spos);

        #pragma unroll
        for (int o = 16; o > 0; o >>= 1) {
            vmax = fmaxf(vmax, __shfl_xor_sync(0xffffffffu, vmax, o));
            spos = fmaxf(spos, __shfl_xor_sync(0xffffffffu, spos, o));
        }

        if (lane == 0) {
            const float s_neg = (lbl == 0) ? 0.0f : vmax;
            warp_loss += softplus_g(2.0f * (2.5f - spos))
                       + softplus_g(2.0f * (0.5f + s_neg));
        }

        if (!more) break;
        row = nrow; rp = nrp; lbl = nlbl;
    }

    // Block reduction of per-warp partial sums.
    __shared__ float s_part[WARPS_PER_BLOCK];
    if (lane == 0) s_part[warp] = warp_loss;
    __syncthreads();

    if (threadIdx.x == 0) {
        float blk = 0.0f;
        #pragma unroll
        for (int i = 0; i < WARPS_PER_BLOCK; ++i) blk += s_part[i];
        atomicAdd(&g_acc, (double)blk);
        __threadfence();
        const unsigned int ticket = atomicAdd(&g_done, 1u);
        if (ticket == gridDim.x - 1) {
            *out = (float)(g_acc / (double)NUM_B);
            g_acc = 0.0;
            g_done = 0;
        }
    }
}

extern "C" void kernel_launch(void* const* d_in, const int* in_sizes, int n_in,
                              void* d_out, int out_size)
{
    const float* scores = (const float*)d_in[0];
    const int*   labels = (const int*)d_in[1];
    float*       out    = (float*)d_out;

    ranking_loss_kernel<<<GRID_CTAS, WARPS_PER_BLOCK * 32>>>(scores, labels, out);
}

// round 10
// speedup vs baseline: 2.1488x; 2.1488x over previous
#include <cuda_runtime.h>
#include <cuda_bf16.h>
#include <math.h>

// RankingLoss: B=65536 rows, C=1024 classes, float32 scores, int32 labels.
// loss = mean_b [ log1p(exp(2*(2.5 - s_pos))) + log1p(exp(2*(0.5 + s_neg))) ]
//   s_pos = scores[b, label[b]]
//   s_neg = max_{c != label} scores[b,c]   (0 if label == 0)
// R5 structure (warp/row, two explicit 4xLDG.128 batches, regs<=32) plus:
//   - one label-compare per float4 (select by lblsub)
//   - spos broadcast with a single shfl from the statically-known owner lane

#define NUM_B 65536
#define NUM_C 1024
#define WARPS_PER_BLOCK 8

__device__ double g_acc = 0.0;
__device__ unsigned int g_done = 0;

__device__ __forceinline__ float softplus_g(float t) {
    return (t > 20.0f) ? t : log1pf(__expf(t));
}

// Single compare per float4; label element selected by lblsub.
__device__ __forceinline__ void consume_f4(float4 v, int f4, int lblf4,
                                           int lblsub, float& vmax, float& spos) {
    float a0 = v.x, a1 = v.y, a2 = v.z, a3 = v.w;
    if (f4 == lblf4) {
        if (lblsub == 0) { spos = a0; a0 = -INFINITY; }
        else if (lblsub == 1) { spos = a1; a1 = -INFINITY; }
        else if (lblsub == 2) { spos = a2; a2 = -INFINITY; }
        else                  { spos = a3; a3 = -INFINITY; }
    }
    vmax = fmaxf(vmax, fmaxf(fmaxf(a0, a1), fmaxf(a2, a3)));
}

// minBlocksPerMultiprocessor=8 pins regs<=32 -> 64 warps/SM resident.
__global__ void __launch_bounds__(WARPS_PER_BLOCK * 32, 8)
ranking_loss_kernel(const float* __restrict__ scores,
                    const int* __restrict__ labels,
                    float* __restrict__ out)
{
    const int lane = threadIdx.x & 31;
    const int warp = threadIdx.x >> 5;
    const int row  = blockIdx.x * WARPS_PER_BLOCK + warp;

    const int lbl    = labels[row];
    const int lblf4  = lbl >> 2;
    const int lblsub = lbl & 3;

    const float4* __restrict__ rp =
        (const float4*)(scores + (size_t)row * NUM_C);

    float vmax = -INFINITY;
    float spos = -INFINITY;

    // Two explicit batches of 4 independent LDG.128 (MLP=4, regs held at 32).
    {
        float4 v0 = rp[0 * 32 + lane];
        float4 v1 = rp[1 * 32 + lane];
        float4 v2 = rp[2 * 32 + lane];
        float4 v3 = rp[3 * 32 + lane];
        consume_f4(v0, 0 * 32 + lane, lblf4, lblsub, vmax, spos);
        consume_f4(v1, 1 * 32 + lane, lblf4, lblsub, vmax, spos);
        consume_f4(v2, 2 * 32 + lane, lblf4, lblsub, vmax, spos);
        consume_f4(v3, 3 * 32 + lane, lblf4, lblsub, vmax, spos);
    }
    {
        float4 v0 = rp[4 * 32 + lane];
        float4 v1 = rp[5 * 32 + lane];
        float4 v2 = rp[6 * 32 + lane];
        float4 v3 = rp[7 * 32 + lane];
        consume_f4(v0, 4 * 32 + lane, lblf4, lblsub, vmax, spos);
        consume_f4(v1, 5 * 32 + lane, lblf4, lblsub, vmax, spos);
        consume_f4(v2, 6 * 32 + lane, lblf4, lblsub, vmax, spos);
        consume_f4(v3, 7 * 32 + lane, lblf4, lblsub, vmax, spos);
    }

    // vmax: 5-step warp tree. spos: one shfl from the statically known
    // owning lane (lane = lblf4 & 31, since f4 = w*32 + lane).
    #pragma unroll
    for (int o = 16; o > 0; o >>= 1)
        vmax = fmaxf(vmax, __shfl_xor_sync(0xffffffffu, vmax, o));
    spos = __shfl_sync(0xffffffffu, spos, lblf4 & 31);

    float row_loss = 0.0f;
    if (lane == 0) {
        const float s_neg = (lbl == 0) ? 0.0f : vmax;
        row_loss = softplus_g(2.0f * (2.5f - spos))
                 + softplus_g(2.0f * (0.5f + s_neg));
    }

    __shared__ float s_part[WARPS_PER_BLOCK];
    if (lane == 0) s_part[warp] = row_loss;
    __syncthreads();

    if (threadIdx.x == 0) {
        float blk = 0.0f;
        #pragma unroll
        for (int i = 0; i < WARPS_PER_BLOCK; ++i) blk += s_part[i];
        atomicAdd(&g_acc, (double)blk);
        __threadfence();
        const unsigned int ticket = atomicAdd(&g_done, 1u);
        if (ticket == gridDim.x - 1) {
            *out = (float)(g_acc / (double)NUM_B);
            g_acc = 0.0;
            g_done = 0;
        }
    }
}

extern "C" void kernel_launch(void* const* d_in, const int* in_sizes, int n_in,
                              void* d_out, int out_size)
{
    const float* scores = (const float*)d_in[0];
    const int*   labels = (const int*)d_in[1];
    float*       out    = (float*)d_out;

    const int grid = NUM_B / WARPS_PER_BLOCK;   // 8192
    ranking_loss_kernel<<<grid, WARPS_PER_BLOCK * 32>>>(scores, labels, out);
}